// round 16
// baseline (speedup 1.0000x reference)
#include <cuda_runtime.h>
#include <math.h>

// CTC forward loss, T=512, N=32, C=8000, S=40 (Se = 2S+1 = 81).
//
// LINEAR-domain scaled forward algorithm with a TIME-SKEWED WAVEFRONT.
// One warp per batch element, 3 consecutive states per lane (lanes 0-26 real,
// 27-31 dead). Lane L computes timestep t = i - L at iteration i, so the
// neighbor values it needs (alpha_{t-1} of lane L-1) were produced TWO
// iterations earlier: the shfl is issued at the start of each iteration and
// its result consumed the NEXT iteration -> shuffle latency is fully off the
// critical path. Per-state update remains FADD+FFMA+FMUL:
//   a'[s] = (a[s] + a[s-1] + skip(s)*a[s-2]) * p[t, class(s)]
// p = ex2(lp*INV_LN2 + boost), boost = +13 live / -1e30 dead (dead states and
// dead lanes hold exactly 0 forever; flow is s-increasing so they can't
// corrupt live states).
//
// Renorm: every 8 iterations, multiply a0,a1,a2 AND the in-flight shfl buffer
// b1,b2 by an exact power of two from the warp-max exponent (butterfly spread
// one stage per iteration). Applied unconditionally to every lane, so all
// mixed quantities carry the same accumulated scale; the integer exponent is
// undone once at the end (bit-exact).
//
// Iterations 1..544 (68 blocks of 8). Lane L active for i in [L+1, L+511];
// inactive lanes hold (gated sel). Ring prefetch depth 8, per-lane addresses,
// loads predicated on 1 <= t+8 <= 511.

#define TT 512
#define NB 32
#define CC 8000
#define SS 40
#define SE 81
#define PF 8
#define STRIDE (NB * CC)

#define BOOST    13.0f
#define NEGBIG   (-1.0e30f)
#define INV_LN2  1.44269504088896341f
#define LN2      0.69314718055994531f

__device__ __forceinline__ float ex2f_(float x) {
    float y; asm("ex2.approx.ftz.f32 %0, %1;" : "=f"(y) : "f"(x)); return y;
}
__device__ __forceinline__ float lg2f_(float x) {
    float y; asm("lg2.approx.ftz.f32 %0, %1;" : "=f"(y) : "f"(x)); return y;
}

// One skewed iteration. slot/off are compile-time constants.
//  1. shfl current (pre-update) a1,a2 -> consumed NEXT iteration (latency hidden)
//  2. recurrence uses b1,b2 (shfl result from the PREVIOUS iteration)
//  3. gated commit (inactive lanes hold), refresh b, advance t
#define ITER(slot, off) do {                                                   \
    const float s1_ = __shfl_up_sync(0xffffffffu, a1, 1);                      \
    const float s2_ = __shfl_up_sync(0xffffffffu, a2, 1);                      \
    const float l0 = ex2f_(__fmaf_rn(r0[slot], INV_LN2, bst0));                \
    const float l1 = ex2f_(__fmaf_rn(r1[slot], INV_LN2, bst1));                \
    const float l2 = ex2f_(__fmaf_rn(r2[slot], INV_LN2, bst2));                \
    const bool ldok = (unsigned)(t + 7) < 511u;   /* 1 <= t+8 <= 511 */        \
    if (ldok) {                                                                \
        r0[slot] = __ldg(P0 + (off) * STRIDE);                                 \
        r1[slot] = __ldg(P1 + (off) * STRIDE);                                 \
        r2[slot] = __ldg(P2 + (off) * STRIDE);                                 \
    }                                                                          \
    const float n0 = __fmaf_rn(sk0, b1, a0 + b2) * l0;                         \
    const float n1 = __fmaf_rn(sk1, b2, a1 + a0) * l1;                         \
    const float n2 = __fmaf_rn(sk2, a0, a2 + a1) * l2;                         \
    const bool act = (unsigned)(t - 1) < 511u;    /* 1 <= t <= 511 */          \
    a0 = act ? n0 : a0;                                                        \
    a1 = act ? n1 : a1;                                                        \
    a2 = act ? n2 : a2;                                                        \
    b1 = lane0 ? 0.0f : s1_;                                                   \
    b2 = lane0 ? 0.0f : s2_;                                                   \
    ++t;                                                                       \
} while (0)

__global__ __launch_bounds__(32, 1)
void ctc_skew_kernel(const float* __restrict__ lp,      // (T, N, C)
                     const int*   __restrict__ targets, // (N, S)
                     const int*   __restrict__ tgt_len, // (N,)
                     float*       __restrict__ out)     // (N,)
{
    const int n    = blockIdx.x;
    const int lane = threadIdx.x;
    const bool lane0 = (lane == 0);
    const int sb   = (lane <= 26) ? 3 * lane : (SE - 3);   // lanes 27-31 dead
    const int Ln   = tgt_len[n];
    const int smax = 2 * Ln;                               // highest live state

    const int* tg = targets + n * SS;
    int   cls[3];
    float skf[3], bst[3];
#pragma unroll
    for (int k = 0; k < 3; ++k) {
        const int s = sb + k;
        if (s & 1) {
            cls[k] = tg[s >> 1];
            skf[k] = (s >= 3 && cls[k] != tg[(s - 3) >> 1]) ? 1.0f : 0.0f;
        } else {
            cls[k] = 0;
            skf[k] = 0.0f;
        }
        bst[k] = (lane <= 26 && s <= smax) ? BOOST : NEGBIG;
    }
    const float sk0 = skf[0], sk1 = skf[1], sk2 = skf[2];
    const float bst0 = bst[0], bst1 = bst[1], bst2 = bst[2];

    const float* q0 = lp + (unsigned)n * CC + (unsigned)cls[0];
    const float* q1 = lp + (unsigned)n * CC + (unsigned)cls[1];
    const float* q2 = lp + (unsigned)n * CC + (unsigned)cls[2];

    // t = 0 init (boosted linear domain); only lane 0's states 0,1 nonzero.
    float a0 = 0.0f, a1 = 0.0f, a2 = 0.0f;
    if (sb == 0) {
        a0 = ex2f_(__fmaf_rn(__ldg(q0), INV_LN2, BOOST));
        a1 = ex2f_(__fmaf_rn(__ldg(q1), INV_LN2, BOOST));
    }
    float b1 = 0.0f, b2 = 0.0f;          // neighbor buffer (consumed at i=1)

    // Ring prefill for consumption at iterations i0 = 1..8 (lane timestep
    // t = i0 - lane; values with t < 1 are never consumed -> clamp address).
    float r0[PF], r1[PF], r2[PF];
#pragma unroll
    for (int i0 = 1; i0 <= 8; ++i0) {
        int tp = i0 - lane; tp = (tp < 0) ? 0 : tp;   // tp <= 8 < 512
        const int sl = i0 & 7;
        const size_t o = (size_t)tp * STRIDE;
        r0[sl] = __ldg(q0 + o);
        r1[sl] = __ldg(q1 + o);
        r2[sl] = __ldg(q2 + o);
    }

    // Per-lane reload base: at iteration i the load target is t+8 = i-lane+8.
    // Block blk covers i = 8*blk+1 .. 8*blk+8 with slots 1..7,0 and immediate
    // offsets 1..7,8 relative to P = q + (8*blk + 8 - lane)*STRIDE.
    const float* P0 = q0 + (ptrdiff_t)(8 - lane) * STRIDE;
    const float* P1 = q1 + (ptrdiff_t)(8 - lane) * STRIDE;
    const float* P2 = q2 + (ptrdiff_t)(8 - lane) * STRIDE;

    int t   = 1 - lane;   // lane timestep at the upcoming iteration
    int lcr = 0;          // accumulated renorm log2 (warp-uniform)

    // 68 blocks of 8 iterations = 544 >= 537 (= 511 + 26 drain).
#pragma unroll 1
    for (int blk = 0; blk < 68; ++blk) {
        float m;
        ITER(1, 1); m = fmaxf(fmaxf(a0, a1), a2);
        ITER(2, 2); m = fmaxf(m, __shfl_xor_sync(0xffffffffu, m, 1));
        ITER(3, 3); m = fmaxf(m, __shfl_xor_sync(0xffffffffu, m, 2));
        ITER(4, 4); m = fmaxf(m, __shfl_xor_sync(0xffffffffu, m, 4));
        ITER(5, 5); m = fmaxf(m, __shfl_xor_sync(0xffffffffu, m, 8));
        ITER(6, 6); m = fmaxf(m, __shfl_xor_sync(0xffffffffu, m, 16));
        int g; float sc;
        ITER(7, 7);
        {
            const int E = (__float_as_int(m) >> 23) & 255;  // m > 0 always
            g  = 127 - E;                                   // scale = 2^g exact
            sc = __int_as_float((127 + g) << 23);
        }
        ITER(0, 8);
        a0 *= sc; a1 *= sc; a2 *= sc;
        b1 *= sc; b2 *= sc;              // keep in-flight buffer consistent
        lcr += g;
        P0 += 8 * STRIDE; P1 += 8 * STRIDE; P2 += 8 * STRIDE;
    }

    // Publish final alphas (each lane holds its alpha_511, uniformly scaled).
    __shared__ float fin[SE];
    if (lane <= 26) { fin[sb] = a0; fin[sb + 1] = a1; fin[sb + 2] = a2; }
    __syncwarp();

    if (lane == 0) {
        const int   len  = 2 * Ln + 1;
        const float ssum = fin[len - 1] + fin[len - 2];
        int e2; const float mant = frexpf(ssum, &e2);
        const float log2a = lg2f_(mant) + (float)e2;
        // Undo renorms and the 512 boosts (t=0 init + 511 steps).
        const float logP_ln = (log2a - (float)lcr - BOOST * 512.0f) * LN2;
        out[n] = -logP_ln / (float)Ln;
    }
}

extern "C" void kernel_launch(void* const* d_in, const int* in_sizes, int n_in,
                              void* d_out, int out_size) {
    const float* lp      = (const float*)d_in[0];  // log_probs (T, N, C)
    const int*   targets = (const int*)  d_in[1];  // (N, S)
    // d_in[2] = input_lengths — reference ignores them (always full T)
    const int*   tlen    = (const int*)  d_in[3];  // (N,)
    ctc_skew_kernel<<<NB, 32>>>(lp, targets, tlen, (float*)d_out);
}

// round 17
// speedup vs baseline: 1.4438x; 1.4438x over previous
#include <cuda_runtime.h>
#include <math.h>

// CTC forward loss, T=512, N=32, C=8000, S=40 (Se = 2S+1 = 81).
//
// TWO-KERNEL split:
//  1) gather_kernel (parallel): p[n][t][k*32+lane] = ex2(lp[t,n,cls]*INV_LN2
//     + boost), boost = +13 live / -1e30 dead — bit-identical to the in-loop
//     expression of the previous best kernel. Packed coalesced, fits L2.
//  2) scan_kernel (sequential): linear-domain scaled forward recurrence,
//     one warp per batch element, 3 states per lane:
//       a'[s] = (a[s] + a[s-1] + skip(s)*a[s-2]) * p
//     Each step reads three 128B coalesced lines (3 L1tex wavefronts) instead
//     of ~85 wavefronts of random gathers — the measured binder of R12.
//     Exact power-of-two warp renorm every 8 steps (butterfly spread one
//     stage per step), integer exponent undone at the end. FP op sequence of
//     the recurrence is identical to the 55.8us kernel.

#define TT 512
#define NB 32
#define CC 8000
#define SS 40
#define SE 81
#define PF 8
#define PKW 96                       // packed row width (3 slots x 32 lanes)

#define BOOST    13.0f
#define NEGBIG   (-1.0e30f)
#define INV_LN2  1.44269504088896341f
#define LN2      0.69314718055994531f

// Packed probs + 8 steps of overrun padding (reload of t=512 is issued but
// never consumed; keep the address in-bounds).
__device__ float g_pk[(TT * NB + 8) * PKW];

__device__ __forceinline__ float ex2f_(float x) {
    float y; asm("ex2.approx.ftz.f32 %0, %1;" : "=f"(y) : "f"(x)); return y;
}
__device__ __forceinline__ float lg2f_(float x) {
    float y; asm("lg2.approx.ftz.f32 %0, %1;" : "=f"(y) : "f"(x)); return y;
}

// ---------------- gather / exponentiate (parallel) ----------------
__global__ __launch_bounds__(PKW)
void ctc_gather_kernel(const float* __restrict__ lp,      // (T, N, C)
                       const int*   __restrict__ targets, // (N, S)
                       const int*   __restrict__ tgt_len) // (N,)
{
    const int t    = blockIdx.x;
    const int n    = blockIdx.y;
    const int tid  = threadIdx.x;          // 0..95
    const int lane = tid & 31;
    const int k    = tid >> 5;             // slot 0..2
    const int s    = 3 * lane + k;         // state (valid for lane <= 26)

    const int* tg = targets + n * SS;
    int cls = 0;
    if (lane <= 26 && (s & 1)) cls = tg[s >> 1];
    const int  smax = 2 * tgt_len[n];
    const float bst = (lane <= 26 && s <= smax) ? BOOST : NEGBIG;

    const float v = __ldg(lp + ((size_t)t * NB + n) * CC + (unsigned)cls);
    g_pk[((size_t)n * TT + t) * PKW + tid] = ex2f_(__fmaf_rn(v, INV_LN2, bst));
}

// ---------------- sequential scan ----------------
// Core recurrence on ring slot j; l's come from the ring (loaded 8 steps ago).
#define STEP_CORE(j) do {                                                      \
    const float l0 = r0[j], l1 = r1[j], l2 = r2[j];                            \
    float p1v = __shfl_up_sync(0xffffffffu, a1, 1);                            \
    float p2v = __shfl_up_sync(0xffffffffu, a2, 1);                            \
    p1v = lane0 ? 0.0f : p1v;                                                  \
    p2v = lane0 ? 0.0f : p2v;                                                  \
    const float n0 = __fmaf_rn(sk0, p1v, a0 + p2v) * l0;                       \
    const float n1 = __fmaf_rn(sk1, p2v, a1 + a0)  * l1;                       \
    const float n2 = __fmaf_rn(sk2, a0,  a2 + a1)  * l2;                       \
    a0 = n0; a1 = n1; a2 = n2;                                                 \
} while (0)

// Step with unconditional coalesced ring reload (compile-time offsets).
#define STEP_R(j) do {                                                         \
    const float t0 = __ldg(P + (j) * PKW);                                     \
    const float t1 = __ldg(P + (j) * PKW + 32);                                \
    const float t2 = __ldg(P + (j) * PKW + 64);                                \
    STEP_CORE(j);                                                              \
    r0[j] = t0; r1[j] = t1; r2[j] = t2;                                        \
} while (0)

#define STEP_N(j) STEP_CORE(j)

__global__ __launch_bounds__(32, 1)
void ctc_scan_kernel(const int* __restrict__ targets, // (N, S)
                     const int* __restrict__ tgt_len, // (N,)
                     float*     __restrict__ out)     // (N,)
{
    const int n    = blockIdx.x;
    const int lane = threadIdx.x;
    const bool lane0 = (lane == 0);
    const int sb   = (lane <= 26) ? 3 * lane : (SE - 3);   // lanes 27-31 dead
    const int Ln   = tgt_len[n];

    // Skip gates (per-lane constants).
    const int* tg = targets + n * SS;
    float skf[3];
#pragma unroll
    for (int k = 0; k < 3; ++k) {
        const int s = sb + k;
        skf[k] = ((s & 1) && s >= 3 && tg[s >> 1] != tg[(s - 3) >> 1]) ? 1.0f : 0.0f;
    }
    const float sk0 = skf[0], sk1 = skf[1], sk2 = skf[2];

    const float* B = g_pk + (size_t)n * TT * PKW + lane;   // t=0 row, this lane

    // t = 0 init: p already boosted/gated in the packed buffer.
    float a0 = 0.0f, a1 = 0.0f, a2 = 0.0f;
    if (sb == 0) {
        a0 = __ldg(B);          // state 0 (k=0, lane=0)
        a1 = __ldg(B + 32);     // state 1 (k=1, lane=0)
    }

    // Prefetch ring for t = 1..8 (slot j <-> t = j+1).
    float r0[PF], r1[PF], r2[PF];
#pragma unroll
    for (int j = 0; j < PF; ++j) {
        const float* q = B + (size_t)(j + 1) * PKW;
        r0[j] = __ldg(q);
        r1[j] = __ldg(q + 32);
        r2[j] = __ldg(q + 64);
    }

    // Reload pointer: block blk covers t = 8*blk+1 .. 8*blk+8, slot j reloads
    // t = 8*blk+9+j  ->  P = B + (8*blk+9)*PKW, offsets j*PKW (+0/32/64).
    const float* P = B + (size_t)9 * PKW;

    int lcr = 0;   // accumulated renorm log2 (warp-uniform)

    // 63 blocks: t = 1..504; reloads t = 9..512 (512 = padding, unconsumed).
#pragma unroll 1
    for (int blk = 0; blk < 63; ++blk) {
        float m;
        STEP_R(0); m = fmaxf(fmaxf(a0, a1), a2);
        STEP_R(1); m = fmaxf(m, __shfl_xor_sync(0xffffffffu, m, 1));
        STEP_R(2); m = fmaxf(m, __shfl_xor_sync(0xffffffffu, m, 2));
        STEP_R(3); m = fmaxf(m, __shfl_xor_sync(0xffffffffu, m, 4));
        STEP_R(4); m = fmaxf(m, __shfl_xor_sync(0xffffffffu, m, 8));
        STEP_R(5); m = fmaxf(m, __shfl_xor_sync(0xffffffffu, m, 16));
        int g; float sc;
        STEP_R(6);
        {
            const int E = (__float_as_int(m) >> 23) & 255;  // m > 0 (live)
            g  = 127 - E;                                   // scale = 2^g exact
            sc = __int_as_float((127 + g) << 23);
        }
        STEP_R(7);
        a0 *= sc; a1 *= sc; a2 *= sc;
        lcr += g;
        P += 8 * PKW;
    }

    // Final 7 steps: t = 505..511 (slots 0..6), no reloads.
    STEP_N(0); STEP_N(1); STEP_N(2); STEP_N(3);
    STEP_N(4); STEP_N(5); STEP_N(6);

    // Publish final alphas from owner lanes (0..26).
    __shared__ float fin[SE];
    if (lane <= 26) { fin[sb] = a0; fin[sb + 1] = a1; fin[sb + 2] = a2; }
    __syncwarp();

    if (lane == 0) {
        const int   len  = 2 * Ln + 1;
        const float ssum = fin[len - 1] + fin[len - 2];
        int e2; const float mant = frexpf(ssum, &e2);
        const float log2a = lg2f_(mant) + (float)e2;
        const float logP_ln = (log2a - (float)lcr - BOOST * 512.0f) * LN2;
        out[n] = -logP_ln / (float)Ln;
    }
}

extern "C" void kernel_launch(void* const* d_in, const int* in_sizes, int n_in,
                              void* d_out, int out_size) {
    const float* lp      = (const float*)d_in[0];  // log_probs (T, N, C)
    const int*   targets = (const int*)  d_in[1];  // (N, S)
    // d_in[2] = input_lengths — reference ignores them (always full T)
    const int*   tlen    = (const int*)  d_in[3];  // (N,)

    dim3 ggrid(TT, NB);
    ctc_gather_kernel<<<ggrid, PKW>>>(lp, targets, tlen);
    ctc_scan_kernel<<<NB, 32>>>(targets, tlen, (float*)d_out);
}